// round 1
// baseline (speedup 1.0000x reference)
#include <cuda_runtime.h>
#include <cuda_bf16.h>

#define B_ 4
#define T_ 4096
#define C_ 1024
#define H_ 64

// Scratch for Q, K, V projections ([B*T, H] row-major each).
__device__ float g_Q[B_ * T_ * H_];
__device__ float g_K[B_ * T_ * H_];
__device__ float g_V[B_ * T_ * H_];

// ---------------------------------------------------------------------------
// Kernel 1: QKV projection.  Out[r][h] = sum_c X[r][c] * W[h][c]
// X: [B*T, C] row-major.  W: [H, C] row-major (torch Linear layout).
// Block: 128 rows x 64 cols, 256 threads, thread tile 4x8.
// ---------------------------------------------------------------------------
#define QKV_BM 128
#define QKV_BK 64

__global__ __launch_bounds__(256) void qkv_kernel(
    const float* __restrict__ X,
    const float* __restrict__ Wq,
    const float* __restrict__ Wk,
    const float* __restrict__ Wv)
{
    extern __shared__ float sm[];
    float* Xs = sm;                  // [128][65]  (pad 65 -> conflict-free col reads)
    float* Ws = sm + 128 * 65;       // [64][65]

    const float* W;
    float* Out;
    if (blockIdx.y == 0)      { W = Wq; Out = g_Q; }
    else if (blockIdx.y == 1) { W = Wk; Out = g_K; }
    else                      { W = Wv; Out = g_V; }

    const int row0 = blockIdx.x * QKV_BM;
    const int tid  = threadIdx.x;
    const int ty   = tid >> 3;   // 0..31 -> rows ty*4 .. ty*4+3
    const int tx   = tid & 7;    // 0..7  -> cols tx + 8*j

    float acc[4][8];
#pragma unroll
    for (int i = 0; i < 4; i++)
#pragma unroll
        for (int j = 0; j < 8; j++) acc[i][j] = 0.f;

    for (int c0 = 0; c0 < C_; c0 += QKV_BK) {
        // Load X tile: 128 x 64 floats = 2048 float4, 8 per thread.
#pragma unroll
        for (int i = 0; i < 8; i++) {
            int idx = tid + i * 256;
            int r   = idx >> 4;      // /16 float4 per row
            int cg  = idx & 15;
            float4 v = *reinterpret_cast<const float4*>(
                X + (size_t)(row0 + r) * C_ + c0 + cg * 4);
            float* p = Xs + r * 65 + cg * 4;
            p[0] = v.x; p[1] = v.y; p[2] = v.z; p[3] = v.w;
        }
        // Load W tile: 64 x 64 floats = 1024 float4, 4 per thread.
#pragma unroll
        for (int i = 0; i < 4; i++) {
            int idx = tid + i * 256;
            int h   = idx >> 4;
            int cg  = idx & 15;
            float4 v = *reinterpret_cast<const float4*>(
                W + (size_t)h * C_ + c0 + cg * 4);
            float* p = Ws + h * 65 + cg * 4;
            p[0] = v.x; p[1] = v.y; p[2] = v.z; p[3] = v.w;
        }
        __syncthreads();

#pragma unroll 4
        for (int cc = 0; cc < QKV_BK; cc++) {
            float xr[4], wv[8];
#pragma unroll
            for (int i = 0; i < 4; i++) xr[i] = Xs[(ty * 4 + i) * 65 + cc];
#pragma unroll
            for (int j = 0; j < 8; j++) wv[j] = Ws[(tx + 8 * j) * 65 + cc];
#pragma unroll
            for (int i = 0; i < 4; i++)
#pragma unroll
                for (int j = 0; j < 8; j++)
                    acc[i][j] = fmaf(xr[i], wv[j], acc[i][j]);
        }
        __syncthreads();
    }

#pragma unroll
    for (int i = 0; i < 4; i++) {
        size_t rbase = (size_t)(row0 + ty * 4 + i) * H_;
#pragma unroll
        for (int j = 0; j < 8; j++)
            Out[rbase + tx + 8 * j] = acc[i][j];
    }
}

// ---------------------------------------------------------------------------
// Kernel 2: causal flash attention.
// One block = one (batch, 64-query tile).  Bc = 64 keys per inner tile.
// 256 threads; thread tile for S / O is 4x4 (ty: 16 groups of 4 rows,
// tx: 16 groups of 4 cols).  Online softmax, O kept in registers.
// qt is reversed vs blockIdx so the heavy (late-diagonal) tiles launch first.
// ---------------------------------------------------------------------------
#define ABr 64
#define ABc 64

__global__ __launch_bounds__(256) void attn_kernel(
    const int* __restrict__ kmask,
    float* __restrict__ out)
{
    extern __shared__ float sm[];
    float* Vs   = sm;                // [64][64]  (16B aligned for float4)
    float* Qs   = Vs + 64 * 64;      // [64][65]
    float* Ks   = Qs + 64 * 65;      // [64][65]
    float* Ssh  = Ks + 64 * 65;      // [64][65]
    float* mrow = Ssh + 64 * 65;     // [64]
    float* lrow = mrow + 64;         // [64]
    float* arow = lrow + 64;         // [64]
    int*   kms  = (int*)(arow + 64); // [64]

    const int b   = blockIdx.y;
    const int qt  = gridDim.x - 1 - blockIdx.x;  // heavy tiles first
    const int q0  = qt * ABr;
    const int tid = threadIdx.x;
    const int ty  = tid >> 4;   // 0..15 -> rows ty*4..+3
    const int tx  = tid & 15;   // 0..15 -> cols tx*4..+3

    const float* Qg = g_Q + ((size_t)b * T_ + q0) * H_;

    // Load Q tile once: 64x64 floats = 1024 float4, 4 per thread.
#pragma unroll
    for (int i = 0; i < 4; i++) {
        int idx = tid + i * 256;
        int q   = idx >> 4;
        int hg  = idx & 15;
        float4 v = *reinterpret_cast<const float4*>(Qg + q * H_ + hg * 4);
        float* p = Qs + q * 65 + hg * 4;
        p[0] = v.x; p[1] = v.y; p[2] = v.z; p[3] = v.w;
    }
    if (tid < 64) { mrow[tid] = -1e30f; lrow[tid] = 0.f; }

    float o[4][4];
#pragma unroll
    for (int i = 0; i < 4; i++)
#pragma unroll
        for (int j = 0; j < 4; j++) o[i][j] = 0.f;

    for (int kt = 0; kt <= qt; kt++) {
        const float* Kg = g_K + ((size_t)b * T_ + kt * ABc) * H_;
        const float* Vg = g_V + ((size_t)b * T_ + kt * ABc) * H_;

        __syncthreads();  // previous-tile consumers done; Qs/mrow visible (1st iter)

        // Load K and V tiles.
#pragma unroll
        for (int i = 0; i < 4; i++) {
            int idx = tid + i * 256;
            int k   = idx >> 4;
            int hg  = idx & 15;
            float4 v = *reinterpret_cast<const float4*>(Kg + k * H_ + hg * 4);
            float* p = Ks + k * 65 + hg * 4;
            p[0] = v.x; p[1] = v.y; p[2] = v.z; p[3] = v.w;
            float4 w = *reinterpret_cast<const float4*>(Vg + k * H_ + hg * 4);
            *reinterpret_cast<float4*>(Vs + k * 64 + hg * 4) = w;
        }
        if (tid < 64) kms[tid] = kmask[(size_t)b * T_ + kt * ABc + tid];
        __syncthreads();

        // S = Q K^T (per-thread 4x4 tile).
        float s[4][4];
#pragma unroll
        for (int i = 0; i < 4; i++)
#pragma unroll
            for (int j = 0; j < 4; j++) s[i][j] = 0.f;

#pragma unroll 4
        for (int h = 0; h < 64; h++) {
            float qv[4], kv[4];
#pragma unroll
            for (int i = 0; i < 4; i++) qv[i] = Qs[(ty * 4 + i) * 65 + h];
#pragma unroll
            for (int j = 0; j < 4; j++) kv[j] = Ks[(tx * 4 + j) * 65 + h];
#pragma unroll
            for (int i = 0; i < 4; i++)
#pragma unroll
                for (int j = 0; j < 4; j++)
                    s[i][j] = fmaf(qv[i], kv[j], s[i][j]);
        }

        // Scale + causal + key-padding mask, write to Ssh.
        const bool diag = (kt == qt);
#pragma unroll
        for (int i = 0; i < 4; i++) {
            int q = q0 + ty * 4 + i;
#pragma unroll
            for (int j = 0; j < 4; j++) {
                int kl = tx * 4 + j;
                float val = s[i][j] * 0.125f;  // 1/sqrt(64)
                if ((diag && (kt * ABc + kl) > q) || (kms[kl] == 0))
                    val = -1e30f;
                Ssh[(ty * 4 + i) * 65 + kl] = val;
            }
        }
        __syncthreads();

        // Online softmax: 4 threads per row, 16 elements each.
        {
            int r   = tid >> 2;
            int sub = tid & 3;
            float* srow = Ssh + r * 65 + sub * 16;
            float mloc = -1e30f;
#pragma unroll
            for (int e = 0; e < 16; e++) mloc = fmaxf(mloc, srow[e]);
            mloc = fmaxf(mloc, __shfl_xor_sync(0xffffffffu, mloc, 1));
            mloc = fmaxf(mloc, __shfl_xor_sync(0xffffffffu, mloc, 2));
            float mold = mrow[r];
            float mnew = fmaxf(mold, mloc);
            float lloc = 0.f;
#pragma unroll
            for (int e = 0; e < 16; e++) {
                float p = __expf(srow[e] - mnew);
                srow[e] = p;
                lloc += p;
            }
            lloc += __shfl_xor_sync(0xffffffffu, lloc, 1);
            lloc += __shfl_xor_sync(0xffffffffu, lloc, 2);
            if (sub == 0) {
                arow[r] = __expf(mold - mnew);
                mrow[r] = mnew;
                lrow[r] = lrow[r] * arow[r] + lloc;
            }
        }
        __syncthreads();

        // O = O * alpha + P @ V
        float al[4];
#pragma unroll
        for (int i = 0; i < 4; i++) al[i] = arow[ty * 4 + i];
#pragma unroll
        for (int i = 0; i < 4; i++)
#pragma unroll
            for (int j = 0; j < 4; j++) o[i][j] *= al[i];

#pragma unroll 4
        for (int kk = 0; kk < 64; kk++) {
            float pv[4];
#pragma unroll
            for (int i = 0; i < 4; i++) pv[i] = Ssh[(ty * 4 + i) * 65 + kk];
            float4 vv = *reinterpret_cast<const float4*>(Vs + kk * 64 + tx * 4);
#pragma unroll
            for (int i = 0; i < 4; i++) {
                o[i][0] = fmaf(pv[i], vv.x, o[i][0]);
                o[i][1] = fmaf(pv[i], vv.y, o[i][1]);
                o[i][2] = fmaf(pv[i], vv.z, o[i][2]);
                o[i][3] = fmaf(pv[i], vv.w, o[i][3]);
            }
        }
    }

    // Normalize and store (lrow final after last softmax's __syncthreads).
#pragma unroll
    for (int i = 0; i < 4; i++) {
        float linv = 1.f / lrow[ty * 4 + i];
        float4 v = make_float4(o[i][0] * linv, o[i][1] * linv,
                               o[i][2] * linv, o[i][3] * linv);
        *reinterpret_cast<float4*>(
            out + ((size_t)b * T_ + q0 + ty * 4 + i) * H_ + tx * 4) = v;
    }
}

// ---------------------------------------------------------------------------
// Launch
// ---------------------------------------------------------------------------
extern "C" void kernel_launch(void* const* d_in, const int* in_sizes, int n_in,
                              void* d_out, int out_size)
{
    const float* X   = (const float*)d_in[0];
    const float* Wq  = (const float*)d_in[1];
    const float* Wk  = (const float*)d_in[2];
    const float* Wv  = (const float*)d_in[3];
    const int*   msk = (const int*)d_in[4];
    float* out = (float*)d_out;

    const int qkv_smem  = (128 * 65 + 64 * 65) * 4;                 // 49920 B
    const int attn_smem = (64 * 64 + 3 * 64 * 65 + 3 * 64) * 4 + 64 * 4; // 67328 B

    cudaFuncSetAttribute(qkv_kernel,
                         cudaFuncAttributeMaxDynamicSharedMemorySize, qkv_smem);
    cudaFuncSetAttribute(attn_kernel,
                         cudaFuncAttributeMaxDynamicSharedMemorySize, attn_smem);

    dim3 g1(B_ * T_ / QKV_BM, 3);
    qkv_kernel<<<g1, 256, qkv_smem>>>(X, Wq, Wk, Wv);

    dim3 g2(T_ / ABr, B_);
    attn_kernel<<<g2, 256, attn_smem>>>(msk, out);
}

// round 2
// speedup vs baseline: 1.1515x; 1.1515x over previous
#include <cuda_runtime.h>
#include <cuda_bf16.h>

#define B_ 4
#define T_ 4096
#define C_ 1024
#define H_ 64

typedef unsigned long long ull;

// Scratch: Q/K/V projections and pre-transposed weights.
__device__ float g_Q[B_ * T_ * H_];
__device__ float g_K[B_ * T_ * H_];
__device__ float g_V[B_ * T_ * H_];
__device__ float g_Wt[3 * C_ * H_];   // [w][c][h]

// ---- packed f32x2 helpers (FFMA2 path; ptxas never emits it from C++) ----
__device__ __forceinline__ ull dup2(float x) {
    ull r; asm("mov.b64 %0, {%1, %1};" : "=l"(r) : "f"(x)); return r;
}
__device__ __forceinline__ ull fma2(ull a, ull b, ull c) {
    ull d; asm("fma.rn.f32x2 %0, %1, %2, %3;" : "=l"(d) : "l"(a), "l"(b), "l"(c)); return d;
}
__device__ __forceinline__ ull mul2(ull a, ull b) {
    ull d; asm("mul.rn.f32x2 %0, %1, %2;" : "=l"(d) : "l"(a), "l"(b)); return d;
}
__device__ __forceinline__ void unpack2(ull v, float& lo, float& hi) {
    asm("mov.b64 {%0, %1}, %2;" : "=f"(lo), "=f"(hi) : "l"(v));
}

// ---------------------------------------------------------------------------
// Kernel 0: transpose W[h][c] -> g_Wt[w][c][h]  (once per call, ~3us)
// ---------------------------------------------------------------------------
__global__ __launch_bounds__(256) void wtrans_kernel(
    const float* __restrict__ Wq,
    const float* __restrict__ Wk,
    const float* __restrict__ Wv)
{
    int idx = blockIdx.x * 256 + threadIdx.x;     // 0 .. 3*65536-1
    int w   = idx >> 16;
    int rem = idx & 65535;
    int c   = rem >> 6;
    int h   = rem & 63;
    const float* W = (w == 0) ? Wq : (w == 1) ? Wk : Wv;
    g_Wt[idx] = W[h * C_ + c];
}

// ---------------------------------------------------------------------------
// Kernel 1: QKV projection with f32x2 FMA.
// Out[r][h] = sum_c X[r][c] * W[h][c].  Block: 128 rows x 64 h, 256 threads,
// thread tile 4 rows x 8 h (4 f32x2 pairs).  W read pre-transposed (h contig).
// ---------------------------------------------------------------------------
__global__ __launch_bounds__(256, 3) void qkv_kernel(const float* __restrict__ X)
{
    extern __shared__ float sm[];
    float* Xs  = sm;             // [128][65]
    float* Wts = sm + 128 * 65;  // [64][64]  (c-major, h contiguous)

    const int w = blockIdx.y;
    const float* Wt = g_Wt + w * (C_ * H_);
    float* Out = (w == 0) ? g_Q : (w == 1) ? g_K : g_V;

    const int row0 = blockIdx.x * 128;
    const int tid  = threadIdx.x;
    const int ty   = tid >> 3;   // 0..31 -> rows ty*4..+3
    const int tx   = tid & 7;    // 0..7  -> cols tx*8..+7

    ull acc2[4][4];
#pragma unroll
    for (int i = 0; i < 4; i++)
#pragma unroll
        for (int jp = 0; jp < 4; jp++) acc2[i][jp] = 0ull;

    for (int c0 = 0; c0 < C_; c0 += 64) {
        __syncthreads();
        // X tile 128x64: 2048 float4
#pragma unroll
        for (int i2 = 0; i2 < 8; i2++) {
            int idx = tid + i2 * 256;
            int r   = idx >> 4;
            int cg  = idx & 15;
            float4 v = *reinterpret_cast<const float4*>(
                X + (size_t)(row0 + r) * C_ + c0 + cg * 4);
            float* p = Xs + r * 65 + cg * 4;
            p[0] = v.x; p[1] = v.y; p[2] = v.z; p[3] = v.w;
        }
        // W tile 64(c) x 64(h): 1024 float4, already transposed -> no conflicts
#pragma unroll
        for (int i2 = 0; i2 < 4; i2++) {
            int idx = tid + i2 * 256;
            int cc  = idx >> 4;
            int hg  = idx & 15;
            float4 v = *reinterpret_cast<const float4*>(
                Wt + (size_t)(c0 + cc) * H_ + hg * 4);
            *reinterpret_cast<float4*>(Wts + cc * 64 + hg * 4) = v;
        }
        __syncthreads();

#pragma unroll 2
        for (int cc = 0; cc < 64; cc++) {
            ull ww[4];
#pragma unroll
            for (int jp = 0; jp < 4; jp++)
                ww[jp] = *reinterpret_cast<const ull*>(Wts + cc * 64 + tx * 8 + 2 * jp);
#pragma unroll
            for (int i = 0; i < 4; i++) {
                ull xx = dup2(Xs[(ty * 4 + i) * 65 + cc]);
#pragma unroll
                for (int jp = 0; jp < 4; jp++)
                    acc2[i][jp] = fma2(xx, ww[jp], acc2[i][jp]);
            }
        }
    }

#pragma unroll
    for (int i = 0; i < 4; i++) {
        size_t rbase = (size_t)(row0 + ty * 4 + i) * H_;
        ulonglong2 a; a.x = acc2[i][0]; a.y = acc2[i][1];
        *reinterpret_cast<ulonglong2*>(Out + rbase + tx * 8) = a;
        ulonglong2 b; b.x = acc2[i][2]; b.y = acc2[i][3];
        *reinterpret_cast<ulonglong2*>(Out + rbase + tx * 8 + 4) = b;
    }
}

// ---------------------------------------------------------------------------
// Kernel 2: causal flash attention, f32x2 FMA, register softmax state.
// 64x64 tiles, 256 threads, thread tile 4 rows x 4 cols.
// S gemm packs query-row pairs (Q transposed in smem); PV packs col pairs.
// m/l/alpha live in registers (all 16 tx lanes redundant); only the two
// block-wide syncs protecting Ks/Vs remain, P handoff is __syncwarp.
// ---------------------------------------------------------------------------
__global__ __launch_bounds__(256, 2) void attn_kernel(
    const int* __restrict__ kmask,
    float* __restrict__ out)
{
    extern __shared__ float sm[];
    float* Vs  = sm;               // [64][64]
    float* Qt  = Vs + 64 * 64;     // [64 h][66]  transposed Q
    float* Ks  = Qt + 64 * 66;     // [64 k][65]
    float* Ssh = Ks + 64 * 65;     // [64 q][66]
    int*   kms = (int*)(Ssh + 64 * 66);  // [64]

    // Heavy/light pairing: bid and bid+148 share an SM (bid % 148).
    const int bid = blockIdx.x;
    const int t   = (bid < 148) ? bid : (403 - bid);   // task rank, 0 = heaviest
    const int qt  = 63 - (t >> 2);
    const int b   = t & 3;
    const int q0  = qt * 64;

    const int tid = threadIdx.x;
    const int ty  = tid >> 4;   // 0..15 -> rows ty*4..+3
    const int tx  = tid & 15;   // 0..15 -> cols tx*4..+3
    const int ty4 = ty * 4, tx4 = tx * 4;

    const float* Qg = g_Q + ((size_t)b * T_ + q0) * H_;

    // Load Q transposed: Qt[h][q]
#pragma unroll
    for (int i2 = 0; i2 < 4; i2++) {
        int idx = tid + i2 * 256;
        int q   = idx >> 4;
        int hg  = idx & 15;
        float4 v = *reinterpret_cast<const float4*>(Qg + q * H_ + hg * 4);
        Qt[(hg * 4 + 0) * 66 + q] = v.x;
        Qt[(hg * 4 + 1) * 66 + q] = v.y;
        Qt[(hg * 4 + 2) * 66 + q] = v.z;
        Qt[(hg * 4 + 3) * 66 + q] = v.w;
    }

    float m[4], l[4];
#pragma unroll
    for (int i = 0; i < 4; i++) { m[i] = -1e30f; l[i] = 0.f; }
    ull o2[4][2];
#pragma unroll
    for (int i = 0; i < 4; i++) { o2[i][0] = 0ull; o2[i][1] = 0ull; }

    for (int kt = 0; kt <= qt; kt++) {
        const float* Kg = g_K + ((size_t)b * T_ + kt * 64) * H_;
        const float* Vg = g_V + ((size_t)b * T_ + kt * 64) * H_;

        __syncthreads();   // prev-iter consumers of Ks/Vs done (also covers Qt init)

#pragma unroll
        for (int i2 = 0; i2 < 4; i2++) {
            int idx = tid + i2 * 256;
            int k   = idx >> 4;
            int hg  = idx & 15;
            float4 v = *reinterpret_cast<const float4*>(Kg + k * H_ + hg * 4);
            float* p = Ks + k * 65 + hg * 4;
            p[0] = v.x; p[1] = v.y; p[2] = v.z; p[3] = v.w;
            float4 w = *reinterpret_cast<const float4*>(Vg + k * H_ + hg * 4);
            *reinterpret_cast<float4*>(Vs + k * 64 + hg * 4) = w;
        }
        if (tid < 64) kms[tid] = kmask[(size_t)b * T_ + kt * 64 + tid];
        __syncthreads();

        int km[4];
#pragma unroll
        for (int j = 0; j < 4; j++) km[j] = kms[tx4 + j];

        // ---- S = Q K^T, row-pairs packed ----
        ull s2[2][4];
#pragma unroll
        for (int j = 0; j < 4; j++) { s2[0][j] = 0ull; s2[1][j] = 0ull; }

#pragma unroll 2
        for (int h = 0; h < 64; h++) {
            ull qq0 = *reinterpret_cast<const ull*>(Qt + h * 66 + ty4);
            ull qq1 = *reinterpret_cast<const ull*>(Qt + h * 66 + ty4 + 2);
#pragma unroll
            for (int j = 0; j < 4; j++) {
                ull kk = dup2(Ks[(tx4 + j) * 65 + h]);
                s2[0][j] = fma2(qq0, kk, s2[0][j]);
                s2[1][j] = fma2(qq1, kk, s2[1][j]);
            }
        }

        // Unpack to scalars
        float s[4][4];
#pragma unroll
        for (int ip = 0; ip < 2; ip++)
#pragma unroll
            for (int j = 0; j < 4; j++)
                unpack2(s2[ip][j], s[2 * ip][j], s[2 * ip + 1][j]);

        const bool diag = (kt == qt);

        // ---- masked online softmax, state in registers ----
#pragma unroll
        for (int i = 0; i < 4; i++) {
            int q = q0 + ty4 + i;
            float v0 = s[i][0] * 0.125f, v1 = s[i][1] * 0.125f;
            float v2 = s[i][2] * 0.125f, v3 = s[i][3] * 0.125f;
            int kb = kt * 64 + tx4;
            if ((diag && kb + 0 > q) || km[0] == 0) v0 = -1e30f;
            if ((diag && kb + 1 > q) || km[1] == 0) v1 = -1e30f;
            if ((diag && kb + 2 > q) || km[2] == 0) v2 = -1e30f;
            if ((diag && kb + 3 > q) || km[3] == 0) v3 = -1e30f;

            float mx = fmaxf(fmaxf(v0, v1), fmaxf(v2, v3));
            mx = fmaxf(mx, __shfl_xor_sync(0xffffffffu, mx, 1));
            mx = fmaxf(mx, __shfl_xor_sync(0xffffffffu, mx, 2));
            mx = fmaxf(mx, __shfl_xor_sync(0xffffffffu, mx, 4));
            mx = fmaxf(mx, __shfl_xor_sync(0xffffffffu, mx, 8));

            float mnew  = fmaxf(m[i], mx);
            float alpha = __expf(m[i] - mnew);
            m[i] = mnew;

            float p0 = __expf(v0 - mnew), p1 = __expf(v1 - mnew);
            float p2 = __expf(v2 - mnew), p3 = __expf(v3 - mnew);
            float ls = (p0 + p1) + (p2 + p3);
            ls += __shfl_xor_sync(0xffffffffu, ls, 1);
            ls += __shfl_xor_sync(0xffffffffu, ls, 2);
            ls += __shfl_xor_sync(0xffffffffu, ls, 4);
            ls += __shfl_xor_sync(0xffffffffu, ls, 8);
            l[i] = l[i] * alpha + ls;

            float2 w0; w0.x = p0; w0.y = p1;
            float2 w1; w1.x = p2; w1.y = p3;
            *reinterpret_cast<float2*>(Ssh + (ty4 + i) * 66 + tx4)     = w0;
            *reinterpret_cast<float2*>(Ssh + (ty4 + i) * 66 + tx4 + 2) = w1;

            ull aa = dup2(alpha);
            o2[i][0] = mul2(o2[i][0], aa);
            o2[i][1] = mul2(o2[i][1], aa);
        }
        __syncwarp();   // P rows produced & consumed within this warp

        // ---- O += P @ V, col-pairs packed ----
#pragma unroll 2
        for (int k = 0; k < 64; k++) {
            ulonglong2 vv = *reinterpret_cast<const ulonglong2*>(Vs + k * 64 + tx4);
#pragma unroll
            for (int i = 0; i < 4; i++) {
                ull pp = dup2(Ssh[(ty4 + i) * 66 + k]);
                o2[i][0] = fma2(pp, vv.x, o2[i][0]);
                o2[i][1] = fma2(pp, vv.y, o2[i][1]);
            }
        }
        __syncwarp();   // Ssh reads done before next-iter rewrite by same warp
    }

    // Normalize and store.
#pragma unroll
    for (int i = 0; i < 4; i++) {
        ull li = dup2(1.f / l[i]);
        ulonglong2 w;
        w.x = mul2(o2[i][0], li);
        w.y = mul2(o2[i][1], li);
        *reinterpret_cast<ulonglong2*>(
            out + ((size_t)b * T_ + q0 + ty4 + i) * H_ + tx4) = w;
    }
}

// ---------------------------------------------------------------------------
// Launch
// ---------------------------------------------------------------------------
extern "C" void kernel_launch(void* const* d_in, const int* in_sizes, int n_in,
                              void* d_out, int out_size)
{
    const float* X   = (const float*)d_in[0];
    const float* Wq  = (const float*)d_in[1];
    const float* Wk  = (const float*)d_in[2];
    const float* Wv  = (const float*)d_in[3];
    const int*   msk = (const int*)d_in[4];
    float* out = (float*)d_out;

    const int qkv_smem  = (128 * 65 + 64 * 64) * 4;                       // 49664 B
    const int attn_smem = (64 * 64 + 64 * 66 + 64 * 65 + 64 * 66) * 4 + 64 * 4; // 67072 B

    cudaFuncSetAttribute(qkv_kernel,
                         cudaFuncAttributeMaxDynamicSharedMemorySize, qkv_smem);
    cudaFuncSetAttribute(attn_kernel,
                         cudaFuncAttributeMaxDynamicSharedMemorySize, attn_smem);

    wtrans_kernel<<<768, 256>>>(Wq, Wk, Wv);

    dim3 g1(B_ * T_ / 128, 3);
    qkv_kernel<<<g1, 256, qkv_smem>>>(X);

    attn_kernel<<<256, 256, attn_smem>>>(msk, out);
}

// round 4
// speedup vs baseline: 2.8359x; 2.4629x over previous
#include <cuda_runtime.h>
#include <cuda_bf16.h>
#include <cstdint>

#define B_ 4
#define T_ 4096
#define C_ 1024
#define H_ 64
#define BT_ (B_ * T_)

// Scratch: bf16 hi/lo splits.
__device__ __nv_bfloat16 g_Qh[BT_ * H_], g_Ql[BT_ * H_];   // [t][h]
__device__ __nv_bfloat16 g_Kh[BT_ * H_], g_Kl[BT_ * H_];   // [t][h]
__device__ __nv_bfloat16 g_Vth[H_ * BT_], g_Vtl[H_ * BT_]; // [h][t]  (transposed!)
__device__ __nv_bfloat16 g_Wh[3 * H_ * C_], g_Wl[3 * H_ * C_]; // [w][h][c]

// ---------------- helpers ----------------
// Split two floats into packed-bf16 hi + packed-bf16 residual-lo (x -> low half).
__device__ __forceinline__ void split2(float x, float y, uint32_t& hi, uint32_t& lo) {
    __nv_bfloat162 h = __float22bfloat162_rn(make_float2(x, y));
    float2 hf = __bfloat1622float2(h);
    __nv_bfloat162 l = __float22bfloat162_rn(make_float2(x - hf.x, y - hf.y));
    hi = *reinterpret_cast<uint32_t*>(&h);
    lo = *reinterpret_cast<uint32_t*>(&l);
}

// bf16 mma m16n8k16, fp32 accumulate (sm_80+, no 'a' feature needed).
__device__ __forceinline__ void mma16816(float* c, const uint32_t* a,
                                         uint32_t b0, uint32_t b1) {
    asm volatile(
        "mma.sync.aligned.m16n8k16.row.col.f32.bf16.bf16.f32 "
        "{%0,%1,%2,%3}, {%4,%5,%6,%7}, {%8,%9}, {%0,%1,%2,%3};"
        : "+f"(c[0]), "+f"(c[1]), "+f"(c[2]), "+f"(c[3])
        : "r"(a[0]), "r"(a[1]), "r"(a[2]), "r"(a[3]), "r"(b0), "r"(b1));
}

// exp2 on the FMA pipe (no MUFU): bit-trick + degree-5 poly. y must be <= ~1.
__device__ __forceinline__ float exp2p(float y) {
    y = fmaxf(y, -80.f);
    float t = y + 12582912.f;                       // 1.5 * 2^23
    int n = __float_as_int(t) - 0x4B400000;
    float f = y - (t - 12582912.f);
    float q = 0.00133335581f;
    q = fmaf(q, f, 0.00961812911f);
    q = fmaf(q, f, 0.0555041087f);
    q = fmaf(q, f, 0.240226507f);
    q = fmaf(q, f, 0.69314718f);
    q = fmaf(q, f, 1.0f);
    return __int_as_float(__float_as_int(q) + (n << 23));
}

// ---------------------------------------------------------------------------
// Kernel 0: split W -> bf16 hi/lo, layout [w][h][c].
// ---------------------------------------------------------------------------
__global__ __launch_bounds__(256) void wsplit_kernel(
    const float* __restrict__ Wq,
    const float* __restrict__ Wk,
    const float* __restrict__ Wv)
{
    int idx = blockIdx.x * 256 + threadIdx.x;
    int w   = idx >> 16;
    int hc  = idx & 65535;
    const float* W = (w == 0) ? Wq : (w == 1) ? Wk : Wv;
    float x = W[hc];
    __nv_bfloat16 h = __float2bfloat16(x);
    g_Wh[idx] = h;
    g_Wl[idx] = __float2bfloat16(x - __bfloat162float(h));
}

// ---------------------------------------------------------------------------
// Kernel 1: QKV projection with mma.sync bf16 3-pass split.
// Grid (BT/128, 3).  CTA: 128 t-rows x 64 h.  8 warps = 4m x 2n,
// per warp 32(m) x 32(n), K=1024 in 16 chunks of 64.
// Writes Q,K hi/lo [t][h]; V hi/lo transposed [h][t].
// ---------------------------------------------------------------------------
__global__ __launch_bounds__(256) void qkv_mma(const float* __restrict__ X)
{
    extern __shared__ char smc[];
    __nv_bfloat16* Xh = (__nv_bfloat16*)smc;        // [128][72]
    __nv_bfloat16* Xl = Xh + 128 * 72;
    __nv_bfloat16* Wh = Xl + 128 * 72;              // [64][72]
    __nv_bfloat16* Wl = Wh + 64 * 72;

    const int wy   = blockIdx.y;
    const int row0 = blockIdx.x * 128;
    const int tid  = threadIdx.x;
    const int lane = tid & 31, warp = tid >> 5;
    const int wm = (warp >> 1) * 32, wn = (warp & 1) * 32;
    const int lr = lane >> 2, lc = (lane & 3) * 2;

    float acc[2][4][4];
#pragma unroll
    for (int mt = 0; mt < 2; mt++)
#pragma unroll
        for (int nt = 0; nt < 4; nt++)
#pragma unroll
            for (int j = 0; j < 4; j++) acc[mt][nt][j] = 0.f;

    const __nv_bfloat16* gWh = g_Wh + (size_t)wy * H_ * C_;
    const __nv_bfloat16* gWl = g_Wl + (size_t)wy * H_ * C_;

    for (int ch = 0; ch < 16; ch++) {
        const int c0 = ch * 64;
        __syncthreads();
        // X chunk: 128x64 fp32 -> bf16 hi/lo
#pragma unroll
        for (int i = 0; i < 4; i++) {
            int g = tid + i * 256;
            int r = g >> 3, c8 = (g & 7) * 8;
            const float4* s = (const float4*)(X + (size_t)(row0 + r) * C_ + c0 + c8);
            float4 a = s[0], b = s[1];
            uint32_t h0, h1, h2, h3, l0, l1, l2, l3;
            split2(a.x, a.y, h0, l0); split2(a.z, a.w, h1, l1);
            split2(b.x, b.y, h2, l2); split2(b.z, b.w, h3, l3);
            *(uint4*)(Xh + r * 72 + c8) = make_uint4(h0, h1, h2, h3);
            *(uint4*)(Xl + r * 72 + c8) = make_uint4(l0, l1, l2, l3);
        }
        // W chunk: 64x64 bf16 hi/lo (pre-split)
#pragma unroll
        for (int i = 0; i < 2; i++) {
            int g = tid + i * 256;
            int r = g >> 3, c8 = (g & 7) * 8;
            *(uint4*)(Wh + r * 72 + c8) = *(const uint4*)(gWh + (size_t)r * C_ + c0 + c8);
            *(uint4*)(Wl + r * 72 + c8) = *(const uint4*)(gWl + (size_t)r * C_ + c0 + c8);
        }
        __syncthreads();

#pragma unroll
        for (int k4 = 0; k4 < 4; k4++) {
            const int kk = k4 * 16 + lc;
            uint32_t ah[2][4], al[2][4];
#pragma unroll
            for (int mt = 0; mt < 2; mt++) {
                int m = wm + mt * 16 + lr;
                ah[mt][0] = *(uint32_t*)(Xh + m * 72 + kk);
                ah[mt][1] = *(uint32_t*)(Xh + (m + 8) * 72 + kk);
                ah[mt][2] = *(uint32_t*)(Xh + m * 72 + kk + 8);
                ah[mt][3] = *(uint32_t*)(Xh + (m + 8) * 72 + kk + 8);
                al[mt][0] = *(uint32_t*)(Xl + m * 72 + kk);
                al[mt][1] = *(uint32_t*)(Xl + (m + 8) * 72 + kk);
                al[mt][2] = *(uint32_t*)(Xl + m * 72 + kk + 8);
                al[mt][3] = *(uint32_t*)(Xl + (m + 8) * 72 + kk + 8);
            }
#pragma unroll
            for (int nt = 0; nt < 4; nt++) {
                int n = wn + nt * 8 + lr;
                uint32_t bh0 = *(uint32_t*)(Wh + n * 72 + kk);
                uint32_t bh1 = *(uint32_t*)(Wh + n * 72 + kk + 8);
                uint32_t bl0 = *(uint32_t*)(Wl + n * 72 + kk);
                uint32_t bl1 = *(uint32_t*)(Wl + n * 72 + kk + 8);
#pragma unroll
                for (int mt = 0; mt < 2; mt++) {
                    mma16816(acc[mt][nt], ah[mt], bh0, bh1);
                    mma16816(acc[mt][nt], ah[mt], bl0, bl1);
                    mma16816(acc[mt][nt], al[mt], bh0, bh1);
                }
            }
        }
    }

    // Store hi/lo splits.
    if (wy < 2) {
        __nv_bfloat16* Oh = wy ? g_Kh : g_Qh;
        __nv_bfloat16* Ol = wy ? g_Kl : g_Ql;
#pragma unroll
        for (int mt = 0; mt < 2; mt++) {
#pragma unroll
            for (int nt = 0; nt < 4; nt++) {
                int r0 = row0 + wm + mt * 16 + lr;
                int cc = wn + nt * 8 + lc;
                uint32_t h01, l01, h23, l23;
                split2(acc[mt][nt][0], acc[mt][nt][1], h01, l01);
                split2(acc[mt][nt][2], acc[mt][nt][3], h23, l23);
                *(uint32_t*)(Oh + (size_t)r0 * H_ + cc)       = h01;
                *(uint32_t*)(Ol + (size_t)r0 * H_ + cc)       = l01;
                *(uint32_t*)(Oh + (size_t)(r0 + 8) * H_ + cc) = h23;
                *(uint32_t*)(Ol + (size_t)(r0 + 8) * H_ + cc) = l23;
            }
        }
    } else {
#pragma unroll
        for (int mt = 0; mt < 2; mt++) {
#pragma unroll
            for (int nt = 0; nt < 4; nt++) {
                int r0 = row0 + wm + mt * 16 + lr;
                int cc = wn + nt * 8 + lc;
#pragma unroll
                for (int j = 0; j < 4; j++) {
                    int rr = r0 + (j >> 1) * 8;
                    int hh = cc + (j & 1);
                    float v = acc[mt][nt][j];
                    __nv_bfloat16 h = __float2bfloat16(v);
                    g_Vth[(size_t)hh * BT_ + rr] = h;
                    g_Vtl[(size_t)hh * BT_ + rr] =
                        __float2bfloat16(v - __bfloat162float(h));
                }
            }
        }
    }
}

// ---------------------------------------------------------------------------
// Kernel 2: causal flash attention on mma.sync.
// CTA = 128 threads (4 warps), one 64-q tile; each warp owns 16 q rows.
// S 3-pass split, P kept in registers (accum->A-frag repack), PV 3-pass.
// exp on FMA pipe via exp2p.  Heavy/light CTA pairing.
// ---------------------------------------------------------------------------
__global__ __launch_bounds__(128, 3) void attn_mma(
    const int* __restrict__ kmask,
    float* __restrict__ out)
{
    extern __shared__ char smc[];
    __nv_bfloat16* Qh  = (__nv_bfloat16*)smc;     // [64][72] each
    __nv_bfloat16* Ql  = Qh  + 64 * 72;
    __nv_bfloat16* Kh  = Ql  + 64 * 72;
    __nv_bfloat16* Kl  = Kh  + 64 * 72;
    __nv_bfloat16* Vth = Kl  + 64 * 72;
    __nv_bfloat16* Vtl = Vth + 64 * 72;
    int* kms = (int*)(Vtl + 64 * 72);             // [64]

    const int bid = blockIdx.x;
    const int t   = (bid < 148) ? bid : (403 - bid);  // heavy tiles first
    const int qt  = 63 - (t >> 2);
    const int b   = t & 3;
    const int q0  = qt * 64;
    const size_t bT = (size_t)b * T_;

    const int tid  = threadIdx.x;
    const int lane = tid & 31, warp = tid >> 5;
    const int qb = warp * 16;
    const int lr = lane >> 2, lc = (lane & 3) * 2;

    // Load Q tile (once).
#pragma unroll
    for (int i = 0; i < 4; i++) {
        int g = tid + i * 128;
        int r = g >> 3, c8 = (g & 7) * 8;
        *(uint4*)(Qh + r * 72 + c8) = *(const uint4*)(g_Qh + (bT + q0 + r) * H_ + c8);
        *(uint4*)(Ql + r * 72 + c8) = *(const uint4*)(g_Ql + (bT + q0 + r) * H_ + c8);
    }
    __syncthreads();

    // Q fragments in registers.
    uint32_t qh[4][4], ql[4][4];
#pragma unroll
    for (int k4 = 0; k4 < 4; k4++) {
        int kk = k4 * 16 + lc;
        qh[k4][0] = *(uint32_t*)(Qh + (qb + lr) * 72 + kk);
        qh[k4][1] = *(uint32_t*)(Qh + (qb + lr + 8) * 72 + kk);
        qh[k4][2] = *(uint32_t*)(Qh + (qb + lr) * 72 + kk + 8);
        qh[k4][3] = *(uint32_t*)(Qh + (qb + lr + 8) * 72 + kk + 8);
        ql[k4][0] = *(uint32_t*)(Ql + (qb + lr) * 72 + kk);
        ql[k4][1] = *(uint32_t*)(Ql + (qb + lr + 8) * 72 + kk);
        ql[k4][2] = *(uint32_t*)(Ql + (qb + lr) * 72 + kk + 8);
        ql[k4][3] = *(uint32_t*)(Ql + (qb + lr + 8) * 72 + kk + 8);
    }

    float m0 = -1e9f, m1 = -1e9f, l0 = 0.f, l1 = 0.f;
    float o[8][4];
#pragma unroll
    for (int nt = 0; nt < 8; nt++)
#pragma unroll
        for (int j = 0; j < 4; j++) o[nt][j] = 0.f;

    const float SCL = 0.18033688f;   // log2(e)/8
    const int qrow = qb + lr;        // local q row (c0,c1); +8 for c2,c3

    for (int kt = 0; kt <= qt; kt++) {
        __syncthreads();
        // Load K, V tiles.
#pragma unroll
        for (int i = 0; i < 4; i++) {
            int g = tid + i * 128;
            int r = g >> 3, c8 = (g & 7) * 8;
            size_t krow = bT + kt * 64 + r;
            *(uint4*)(Kh + r * 72 + c8)  = *(const uint4*)(g_Kh + krow * H_ + c8);
            *(uint4*)(Kl + r * 72 + c8)  = *(const uint4*)(g_Kl + krow * H_ + c8);
            *(uint4*)(Vth + r * 72 + c8) = *(const uint4*)(g_Vth + (size_t)r * BT_ + bT + kt * 64 + c8);
            *(uint4*)(Vtl + r * 72 + c8) = *(const uint4*)(g_Vtl + (size_t)r * BT_ + bT + kt * 64 + c8);
        }
        if (tid < 64) kms[tid] = kmask[bT + kt * 64 + tid];
        __syncthreads();

        // ---- S = Q K^T (3-pass) ----
        float s[8][4];
#pragma unroll
        for (int nt = 0; nt < 8; nt++)
#pragma unroll
            for (int j = 0; j < 4; j++) s[nt][j] = 0.f;

#pragma unroll
        for (int k4 = 0; k4 < 4; k4++) {
            int kk = k4 * 16 + lc;
#pragma unroll
            for (int nt = 0; nt < 8; nt++) {
                int n = nt * 8 + lr;
                uint32_t bh0 = *(uint32_t*)(Kh + n * 72 + kk);
                uint32_t bh1 = *(uint32_t*)(Kh + n * 72 + kk + 8);
                uint32_t bl0 = *(uint32_t*)(Kl + n * 72 + kk);
                uint32_t bl1 = *(uint32_t*)(Kl + n * 72 + kk + 8);
                mma16816(s[nt], qh[k4], bh0, bh1);
                mma16816(s[nt], qh[k4], bl0, bl1);
                mma16816(s[nt], ql[k4], bh0, bh1);
            }
        }

        // ---- mask + scale into base-2 domain ----
        const bool diag = (kt == qt);
        float mx0 = -1e9f, mx1 = -1e9f;
#pragma unroll
        for (int nt = 0; nt < 8; nt++) {
            int c = nt * 8 + lc;
            int km0 = kms[c], km1 = kms[c + 1];
            float v0 = s[nt][0] * SCL, v1 = s[nt][1] * SCL;
            float v2 = s[nt][2] * SCL, v3 = s[nt][3] * SCL;
            if ((diag && c     > qrow)     || !km0) v0 = -1e9f;
            if ((diag && c + 1 > qrow)     || !km1) v1 = -1e9f;
            if ((diag && c     > qrow + 8) || !km0) v2 = -1e9f;
            if ((diag && c + 1 > qrow + 8) || !km1) v3 = -1e9f;
            s[nt][0] = v0; s[nt][1] = v1; s[nt][2] = v2; s[nt][3] = v3;
            mx0 = fmaxf(mx0, fmaxf(v0, v1));
            mx1 = fmaxf(mx1, fmaxf(v2, v3));
        }
        mx0 = fmaxf(mx0, __shfl_xor_sync(0xffffffffu, mx0, 1));
        mx0 = fmaxf(mx0, __shfl_xor_sync(0xffffffffu, mx0, 2));
        mx1 = fmaxf(mx1, __shfl_xor_sync(0xffffffffu, mx1, 1));
        mx1 = fmaxf(mx1, __shfl_xor_sync(0xffffffffu, mx1, 2));

        float mn0 = fmaxf(m0, mx0), mn1 = fmaxf(m1, mx1);
        float a0 = exp2p(m0 - mn0), a1 = exp2p(m1 - mn1);
        m0 = mn0; m1 = mn1;

        float ls0 = 0.f, ls1 = 0.f;
#pragma unroll
        for (int nt = 0; nt < 8; nt++) {
            float p0 = exp2p(s[nt][0] - mn0), p1 = exp2p(s[nt][1] - mn0);
            float p2 = exp2p(s[nt][2] - mn1), p3 = exp2p(s[nt][3] - mn1);
            s[nt][0] = p0; s[nt][1] = p1; s[nt][2] = p2; s[nt][3] = p3;
            ls0 += p0 + p1; ls1 += p2 + p3;
        }
        ls0 += __shfl_xor_sync(0xffffffffu, ls0, 1);
        ls0 += __shfl_xor_sync(0xffffffffu, ls0, 2);
        ls1 += __shfl_xor_sync(0xffffffffu, ls1, 1);
        ls1 += __shfl_xor_sync(0xffffffffu, ls1, 2);
        l0 = l0 * a0 + ls0;
        l1 = l1 * a1 + ls1;

        // Rescale O.
#pragma unroll
        for (int nt = 0; nt < 8; nt++) {
            o[nt][0] *= a0; o[nt][1] *= a0;
            o[nt][2] *= a1; o[nt][3] *= a1;
        }

        // ---- repack P (accum layout -> A-frag layout, in registers) ----
        uint32_t ph[4][4], pl[4][4];
#pragma unroll
        for (int k4 = 0; k4 < 4; k4++) {
            int ta = 2 * k4, tb = ta + 1;
            split2(s[ta][0], s[ta][1], ph[k4][0], pl[k4][0]);
            split2(s[ta][2], s[ta][3], ph[k4][1], pl[k4][1]);
            split2(s[tb][0], s[tb][1], ph[k4][2], pl[k4][2]);
            split2(s[tb][2], s[tb][3], ph[k4][3], pl[k4][3]);
        }

        // ---- O += P V (3-pass) ----
#pragma unroll
        for (int k4 = 0; k4 < 4; k4++) {
            int kk = k4 * 16 + lc;
#pragma unroll
            for (int nt = 0; nt < 8; nt++) {
                int n = nt * 8 + lr;
                uint32_t vh0 = *(uint32_t*)(Vth + n * 72 + kk);
                uint32_t vh1 = *(uint32_t*)(Vth + n * 72 + kk + 8);
                uint32_t vl0 = *(uint32_t*)(Vtl + n * 72 + kk);
                uint32_t vl1 = *(uint32_t*)(Vtl + n * 72 + kk + 8);
                mma16816(o[nt], ph[k4], vh0, vh1);
                mma16816(o[nt], ph[k4], vl0, vl1);
                mma16816(o[nt], pl[k4], vh0, vh1);
            }
        }
    }

    // Epilogue: normalize, store fp32.
    float il0 = 1.f / l0, il1 = 1.f / l1;
    size_t r0 = bT + q0 + qrow;
#pragma unroll
    for (int nt = 0; nt < 8; nt++) {
        int cc = nt * 8 + lc;
        *(float2*)(out + r0 * H_ + cc) =
            make_float2(o[nt][0] * il0, o[nt][1] * il0);
        *(float2*)(out + (r0 + 8) * H_ + cc) =
            make_float2(o[nt][2] * il1, o[nt][3] * il1);
    }
}

// ---------------------------------------------------------------------------
// Launch
// ---------------------------------------------------------------------------
extern "C" void kernel_launch(void* const* d_in, const int* in_sizes, int n_in,
                              void* d_out, int out_size)
{
    const float* X   = (const float*)d_in[0];
    const float* Wq  = (const float*)d_in[1];
    const float* Wk  = (const float*)d_in[2];
    const float* Wv  = (const float*)d_in[3];
    const int*   msk = (const int*)d_in[4];
    float* out = (float*)d_out;

    const int qkv_smem  = (2 * 128 * 72 + 2 * 64 * 72) * 2;           // 55296 B
    const int attn_smem = 6 * 64 * 72 * 2 + 64 * 4;                   // 55552 B

    cudaFuncSetAttribute(qkv_mma,
                         cudaFuncAttributeMaxDynamicSharedMemorySize, qkv_smem);
    cudaFuncSetAttribute(attn_mma,
                         cudaFuncAttributeMaxDynamicSharedMemorySize, attn_smem);

    wsplit_kernel<<<768, 256>>>(Wq, Wk, Wv);

    dim3 g1(BT_ / 128, 3);
    qkv_mma<<<g1, 256, qkv_smem>>>(X);

    attn_mma<<<256, 128, attn_smem>>>(msk, out);
}

// round 5
// speedup vs baseline: 3.9237x; 1.3836x over previous
#include <cuda_runtime.h>
#include <cuda_bf16.h>
#include <cstdint>

#define B_ 4
#define T_ 4096
#define C_ 1024
#define H_ 64
#define BT_ (B_ * T_)

// Scratch: bf16 hi/lo splits, all [t][h] row-major.
__device__ __nv_bfloat16 g_Qh[BT_ * H_], g_Ql[BT_ * H_];
__device__ __nv_bfloat16 g_Kh[BT_ * H_], g_Kl[BT_ * H_];
__device__ __nv_bfloat16 g_Vh[BT_ * H_], g_Vl[BT_ * H_];
__device__ __nv_bfloat16 g_Wh[3 * H_ * C_], g_Wl[3 * H_ * C_]; // [w][h][c]

// ---------------- helpers ----------------
__device__ __forceinline__ uint32_t smem_u32(const void* p) {
    uint32_t a;
    asm("{ .reg .u64 t; cvta.to.shared.u64 t, %1; cvt.u32.u64 %0, t; }" : "=r"(a) : "l"(p));
    return a;
}
__device__ __forceinline__ void split2(float x, float y, uint32_t& hi, uint32_t& lo) {
    __nv_bfloat162 h = __float22bfloat162_rn(make_float2(x, y));
    float2 hf = __bfloat1622float2(h);
    __nv_bfloat162 l = __float22bfloat162_rn(make_float2(x - hf.x, y - hf.y));
    hi = *reinterpret_cast<uint32_t*>(&h);
    lo = *reinterpret_cast<uint32_t*>(&l);
}
__device__ __forceinline__ void mma16816(float* c, const uint32_t* a,
                                         uint32_t b0, uint32_t b1) {
    asm volatile(
        "mma.sync.aligned.m16n8k16.row.col.f32.bf16.bf16.f32 "
        "{%0,%1,%2,%3}, {%4,%5,%6,%7}, {%8,%9}, {%0,%1,%2,%3};"
        : "+f"(c[0]), "+f"(c[1]), "+f"(c[2]), "+f"(c[3])
        : "r"(a[0]), "r"(a[1]), "r"(a[2]), "r"(a[3]), "r"(b0), "r"(b1));
}
__device__ __forceinline__ void ldm_x4(uint32_t* r, uint32_t saddr) {
    asm volatile("ldmatrix.sync.aligned.m8n8.x4.shared.b16 {%0,%1,%2,%3}, [%4];"
        : "=r"(r[0]), "=r"(r[1]), "=r"(r[2]), "=r"(r[3]) : "r"(saddr));
}
__device__ __forceinline__ void ldm_x4t(uint32_t* r, uint32_t saddr) {
    asm volatile("ldmatrix.sync.aligned.m8n8.x4.trans.shared.b16 {%0,%1,%2,%3}, [%4];"
        : "=r"(r[0]), "=r"(r[1]), "=r"(r[2]), "=r"(r[3]) : "r"(saddr));
}
__device__ __forceinline__ void cpa16(uint32_t sdst, const void* gsrc) {
    asm volatile("cp.async.cg.shared.global [%0], [%1], 16;" :: "r"(sdst), "l"(gsrc) : "memory");
}
__device__ __forceinline__ void cpa_commit() {
    asm volatile("cp.async.commit_group;" ::: "memory");
}
__device__ __forceinline__ void cpa_wait1() {
    asm volatile("cp.async.wait_group 1;" ::: "memory");
}
__device__ __forceinline__ void cpa_wait0() {
    asm volatile("cp.async.wait_group 0;" ::: "memory");
}
__device__ __forceinline__ float ex2(float x) {
    float y; asm("ex2.approx.ftz.f32 %0, %1;" : "=f"(y) : "f"(x)); return y;
}

// ---------------------------------------------------------------------------
// Kernel 0: split W -> bf16 hi/lo, layout [w][h][c].
// ---------------------------------------------------------------------------
__global__ __launch_bounds__(256) void wsplit_kernel(
    const float* __restrict__ Wq,
    const float* __restrict__ Wk,
    const float* __restrict__ Wv)
{
    int idx = blockIdx.x * 256 + threadIdx.x;
    int w   = idx >> 16;
    int hc  = idx & 65535;
    const float* W = (w == 0) ? Wq : (w == 1) ? Wk : Wv;
    float x = W[hc];
    __nv_bfloat16 h = __float2bfloat16(x);
    g_Wh[idx] = h;
    g_Wl[idx] = __float2bfloat16(x - __bfloat162float(h));
}

// ---------------------------------------------------------------------------
// Kernel 1: QKV projection, mma.sync 3-pass, software-pipelined:
// X chunk prefetched to registers, W chunk double-buffered via cp.async.
// Grid (BT/128, 3); 256 threads (8 warps = 4m x 2n).
// ---------------------------------------------------------------------------
#define QX_ST 36864          // per X stage: Xh 18432 + Xl 18432
#define QW_ST 18432          // per W stage: Wh 9216 + Wl 9216
#define QKV_SMEM (2 * QX_ST + 2 * QW_ST)

__global__ __launch_bounds__(256, 2) void qkv_mma(const float* __restrict__ X)
{
    extern __shared__ char smc[];
    const uint32_t sb = smem_u32(smc);

    const int wy   = blockIdx.y;
    const int row0 = blockIdx.x * 128;
    const int tid  = threadIdx.x;
    const int lane = tid & 31, warp = tid >> 5;
    const int wm = (warp >> 1) * 32, wn = (warp & 1) * 32;
    const int lr = lane >> 2, lc = (lane & 3) * 2;

    const __nv_bfloat16* gWh = g_Wh + (size_t)wy * H_ * C_;
    const __nv_bfloat16* gWl = g_Wl + (size_t)wy * H_ * C_;

    float acc[2][4][4];
#pragma unroll
    for (int mt = 0; mt < 2; mt++)
#pragma unroll
        for (int nt = 0; nt < 4; nt++)
#pragma unroll
            for (int j = 0; j < 4; j++) acc[mt][nt][j] = 0.f;

    float4 xreg[8];
    // Prologue: X chunk 0 -> regs; W chunk 0 -> cp.async stage 0.
#pragma unroll
    for (int i = 0; i < 4; i++) {
        int g = tid + i * 256;
        int r = g >> 3, c8 = (g & 7) * 8;
        const float4* s = (const float4*)(X + (size_t)(row0 + r) * C_ + c8);
        xreg[2 * i] = s[0]; xreg[2 * i + 1] = s[1];
    }
#pragma unroll
    for (int i = 0; i < 2; i++) {
        int g = tid + i * 256;
        int r = g >> 3, c8 = (g & 7) * 8;
        uint32_t so = (uint32_t)(r * 72 + c8) * 2;
        cpa16(sb + 2 * QX_ST + so,        gWh + (size_t)r * C_ + c8);
        cpa16(sb + 2 * QX_ST + 9216 + so, gWl + (size_t)r * C_ + c8);
    }
    cpa_commit();

    for (int c = 0; c < 16; c++) {
        const int p = c & 1;
        __nv_bfloat16* Xh = (__nv_bfloat16*)(smc + p * QX_ST);
        __nv_bfloat16* Xl = Xh + 18432 / 2;
        __nv_bfloat16* Wh = (__nv_bfloat16*)(smc + 2 * QX_ST + p * QW_ST);
        __nv_bfloat16* Wl = Wh + 9216 / 2;

        // Convert + store current X chunk from registers.
#pragma unroll
        for (int i = 0; i < 4; i++) {
            int g = tid + i * 256;
            int r = g >> 3, c8 = (g & 7) * 8;
            float4 a = xreg[2 * i], b = xreg[2 * i + 1];
            uint32_t h0, h1, h2, h3, l0, l1, l2, l3;
            split2(a.x, a.y, h0, l0); split2(a.z, a.w, h1, l1);
            split2(b.x, b.y, h2, l2); split2(b.z, b.w, h3, l3);
            *(uint4*)(Xh + r * 72 + c8) = make_uint4(h0, h1, h2, h3);
            *(uint4*)(Xl + r * 72 + c8) = make_uint4(l0, l1, l2, l3);
        }
        if (c < 15) {
            const int c1 = (c + 1) * 64;
            // Issue next W chunk.
#pragma unroll
            for (int i = 0; i < 2; i++) {
                int g = tid + i * 256;
                int r = g >> 3, c8 = (g & 7) * 8;
                uint32_t so = (uint32_t)(r * 72 + c8) * 2;
                uint32_t wb = sb + 2 * QX_ST + (p ^ 1) * QW_ST;
                cpa16(wb + so,        gWh + (size_t)r * C_ + c1 + c8);
                cpa16(wb + 9216 + so, gWl + (size_t)r * C_ + c1 + c8);
            }
            cpa_commit();
            // Prefetch next X chunk into registers (latency hidden by MMA).
#pragma unroll
            for (int i = 0; i < 4; i++) {
                int g = tid + i * 256;
                int r = g >> 3, c8 = (g & 7) * 8;
                const float4* s = (const float4*)(X + (size_t)(row0 + r) * C_ + c1 + c8);
                xreg[2 * i] = s[0]; xreg[2 * i + 1] = s[1];
            }
            cpa_wait1();
        } else {
            cpa_wait0();
        }
        __syncthreads();

#pragma unroll
        for (int k4 = 0; k4 < 4; k4++) {
            const int kk = k4 * 16 + lc;
            uint32_t ah[2][4], al[2][4];
#pragma unroll
            for (int mt = 0; mt < 2; mt++) {
                int m = wm + mt * 16 + lr;
                ah[mt][0] = *(uint32_t*)(Xh + m * 72 + kk);
                ah[mt][1] = *(uint32_t*)(Xh + (m + 8) * 72 + kk);
                ah[mt][2] = *(uint32_t*)(Xh + m * 72 + kk + 8);
                ah[mt][3] = *(uint32_t*)(Xh + (m + 8) * 72 + kk + 8);
                al[mt][0] = *(uint32_t*)(Xl + m * 72 + kk);
                al[mt][1] = *(uint32_t*)(Xl + (m + 8) * 72 + kk);
                al[mt][2] = *(uint32_t*)(Xl + m * 72 + kk + 8);
                al[mt][3] = *(uint32_t*)(Xl + (m + 8) * 72 + kk + 8);
            }
#pragma unroll
            for (int nt = 0; nt < 4; nt++) {
                int n = wn + nt * 8 + lr;
                uint32_t bh0 = *(uint32_t*)(Wh + n * 72 + kk);
                uint32_t bh1 = *(uint32_t*)(Wh + n * 72 + kk + 8);
                uint32_t bl0 = *(uint32_t*)(Wl + n * 72 + kk);
                uint32_t bl1 = *(uint32_t*)(Wl + n * 72 + kk + 8);
#pragma unroll
                for (int mt = 0; mt < 2; mt++) {
                    mma16816(acc[mt][nt], ah[mt], bh0, bh1);
                    mma16816(acc[mt][nt], ah[mt], bl0, bl1);
                    mma16816(acc[mt][nt], al[mt], bh0, bh1);
                }
            }
        }
        __syncthreads();
    }

    // Store hi/lo splits (all [t][h]).
    __nv_bfloat16* Oh = (wy == 0) ? g_Qh : (wy == 1) ? g_Kh : g_Vh;
    __nv_bfloat16* Ol = (wy == 0) ? g_Ql : (wy == 1) ? g_Kl : g_Vl;
#pragma unroll
    for (int mt = 0; mt < 2; mt++) {
#pragma unroll
        for (int nt = 0; nt < 4; nt++) {
            int r0 = row0 + wm + mt * 16 + lr;
            int cc = wn + nt * 8 + lc;
            uint32_t h01, l01, h23, l23;
            split2(acc[mt][nt][0], acc[mt][nt][1], h01, l01);
            split2(acc[mt][nt][2], acc[mt][nt][3], h23, l23);
            *(uint32_t*)(Oh + (size_t)r0 * H_ + cc)       = h01;
            *(uint32_t*)(Ol + (size_t)r0 * H_ + cc)       = l01;
            *(uint32_t*)(Oh + (size_t)(r0 + 8) * H_ + cc) = h23;
            *(uint32_t*)(Ol + (size_t)(r0 + 8) * H_ + cc) = l23;
        }
    }
}

// ---------------------------------------------------------------------------
// Kernel 2: causal flash attention, mma.sync + cp.async double buffer +
// ldmatrix frags + MUFU ex2.  128 threads (4 warps), 64-q tile per CTA.
// ---------------------------------------------------------------------------
#define AST 36864                      // per stage: Kh|Kl|Vh|Vl, 9216B each
#define ATTN_SMEM (2 * AST + 512)      // + kms[2][64]

__global__ __launch_bounds__(128, 3) void attn_mma(
    const int* __restrict__ kmask,
    float* __restrict__ out)
{
    extern __shared__ char smc[];
    const uint32_t sb = smem_u32(smc);

    const int bid = blockIdx.x;
    const int t   = (bid < 148) ? bid : (403 - bid);  // heavy tiles first
    const int qt  = 63 - (t >> 2);
    const int b   = t & 3;
    const int q0  = qt * 64;
    const size_t bT = (size_t)b * T_;

    const int tid  = threadIdx.x;
    const int lane = tid & 31, warp = tid >> 5;
    const int qb = warp * 16;
    const int lr = lane >> 2, lc = (lane & 3) * 2;
    const int qrow = qb + lr;

    // ldmatrix lane addressing offsets.
    const int arow  = qb + (lane & 15);            // A (Q) frags
    const int acol8 = (lane & 16) >> 1;
    const int brow  = (lane & 7) + ((lane & 16) >> 1);  // B (K) frags
    const int bcol8 = (lane & 8);
    const int vrow  = lane & 15;                   // B (V, trans) frags
    const int vcol8 = (lane & 16) >> 1;

#define ISSUE_STAGE(s_, kt_) do {                                            \
    const size_t rb_ = bT + (size_t)(kt_) * 64;                              \
    const uint32_t dst_ = sb + (s_) * AST;                                   \
    _Pragma("unroll")                                                        \
    for (int i_ = 0; i_ < 4; i_++) {                                         \
        int g_ = tid + i_ * 128;                                             \
        int r_ = g_ >> 3, c8_ = (g_ & 7) * 8;                                \
        uint32_t so_ = (uint32_t)(r_ * 72 + c8_) * 2;                        \
        cpa16(dst_ + so_,         g_Kh + (rb_ + r_) * H_ + c8_);             \
        cpa16(dst_ + 9216 + so_,  g_Kl + (rb_ + r_) * H_ + c8_);             \
        cpa16(dst_ + 18432 + so_, g_Vh + (rb_ + r_) * H_ + c8_);             \
        cpa16(dst_ + 27648 + so_, g_Vl + (rb_ + r_) * H_ + c8_);             \
    }                                                                        \
    if (tid < 16) cpa16(sb + 2 * AST + (s_) * 256 + tid * 16,                \
                        kmask + rb_ + tid * 4);                              \
} while (0)

    // Prefetch stage 0 (kt = 0).
    ISSUE_STAGE(0, 0);
    cpa_commit();

    // Load Q into stage-1 region (reused; overwritten by kt=1 prefetch later).
#pragma unroll
    for (int i = 0; i < 4; i++) {
        int g = tid + i * 128;
        int r = g >> 3, c8 = (g & 7) * 8;
        *(uint4*)(smc + AST + (r * 72 + c8) * 2) =
            *(const uint4*)(g_Qh + (bT + q0 + r) * H_ + c8);
        *(uint4*)(smc + AST + 9216 + (r * 72 + c8) * 2) =
            *(const uint4*)(g_Ql + (bT + q0 + r) * H_ + c8);
    }
    __syncthreads();

    uint32_t qh[4][4], ql[4][4];
#pragma unroll
    for (int k4 = 0; k4 < 4; k4++) {
        uint32_t off = (uint32_t)(arow * 72 + k4 * 16 + acol8) * 2;
        ldm_x4(qh[k4], sb + AST + off);
        ldm_x4(ql[k4], sb + AST + 9216 + off);
    }
    __syncthreads();   // Q frags extracted before stage 1 is refilled

    float m0 = -1e9f, m1 = -1e9f, l0 = 0.f, l1 = 0.f;
    float o[8][4];
#pragma unroll
    for (int nt = 0; nt < 8; nt++)
#pragma unroll
        for (int j = 0; j < 4; j++) o[nt][j] = 0.f;

    const float SCL = 0.18033688f;   // log2(e)/8

    for (int kt = 0; kt <= qt; kt++) {
        const int s = kt & 1;
        if (kt < qt) {
            ISSUE_STAGE(s ^ 1, kt + 1);
            cpa_commit();
            cpa_wait1();
        } else {
            cpa_wait0();
        }
        __syncthreads();

        const uint32_t kh = sb + s * AST;
        const uint32_t kl = kh + 9216;
        const uint32_t vh = kh + 18432;
        const uint32_t vl = kh + 27648;
        const int* kms = (const int*)(smc + 2 * AST + s * 256);

        // ---- S = Q K^T (3-pass) ----
        float sa[8][4];
#pragma unroll
        for (int nt = 0; nt < 8; nt++)
#pragma unroll
            for (int j = 0; j < 4; j++) sa[nt][j] = 0.f;

#pragma unroll
        for (int k4 = 0; k4 < 4; k4++) {
            const int kk = k4 * 16;
#pragma unroll
            for (int p = 0; p < 4; p++) {
                uint32_t bh[4], bl[4];
                uint32_t off = (uint32_t)((p * 16 + brow) * 72 + kk + bcol8) * 2;
                ldm_x4(bh, kh + off);
                ldm_x4(bl, kl + off);
                mma16816(sa[2 * p],     qh[k4], bh[0], bh[1]);
                mma16816(sa[2 * p],     qh[k4], bl[0], bl[1]);
                mma16816(sa[2 * p],     ql[k4], bh[0], bh[1]);
                mma16816(sa[2 * p + 1], qh[k4], bh[2], bh[3]);
                mma16816(sa[2 * p + 1], qh[k4], bl[2], bl[3]);
                mma16816(sa[2 * p + 1], ql[k4], bh[2], bh[3]);
            }
        }

        // ---- mask + scale (base-2 domain) ----
        const bool diag = (kt == qt);
        float mx0 = -1e9f, mx1 = -1e9f;
#pragma unroll
        for (int nt = 0; nt < 8; nt++) {
            int c = nt * 8 + lc;
            float am0 = kms[c]     ? 0.f : -1e9f;
            float am1 = kms[c + 1] ? 0.f : -1e9f;
            float v0 = fmaf(sa[nt][0], SCL, am0);
            float v1 = fmaf(sa[nt][1], SCL, am1);
            float v2 = fmaf(sa[nt][2], SCL, am0);
            float v3 = fmaf(sa[nt][3], SCL, am1);
            if (diag) {
                if (c     > qrow)     v0 = -1e9f;
                if (c + 1 > qrow)     v1 = -1e9f;
                if (c     > qrow + 8) v2 = -1e9f;
                if (c + 1 > qrow + 8) v3 = -1e9f;
            }
            sa[nt][0] = v0; sa[nt][1] = v1; sa[nt][2] = v2; sa[nt][3] = v3;
            mx0 = fmaxf(mx0, fmaxf(v0, v1));
            mx1 = fmaxf(mx1, fmaxf(v2, v3));
        }
        mx0 = fmaxf(mx0, __shfl_xor_sync(0xffffffffu, mx0, 1));
        mx0 = fmaxf(mx0, __shfl_xor_sync(0xffffffffu, mx0, 2));
        mx1 = fmaxf(mx1, __shfl_xor_sync(0xffffffffu, mx1, 1));
        mx1 = fmaxf(mx1, __shfl_xor_sync(0xffffffffu, mx1, 2));

        float mn0 = fmaxf(m0, mx0), mn1 = fmaxf(m1, mx1);
        float a0 = ex2(m0 - mn0), a1 = ex2(m1 - mn1);
        m0 = mn0; m1 = mn1;

        float ls0 = 0.f, ls1 = 0.f;
#pragma unroll
        for (int nt = 0; nt < 8; nt++) {
            float p0 = ex2(sa[nt][0] - mn0), p1 = ex2(sa[nt][1] - mn0);
            float p2 = ex2(sa[nt][2] - mn1), p3 = ex2(sa[nt][3] - mn1);
            sa[nt][0] = p0; sa[nt][1] = p1; sa[nt][2] = p2; sa[nt][3] = p3;
            ls0 += p0 + p1; ls1 += p2 + p3;
        }
        ls0 += __shfl_xor_sync(0xffffffffu, ls0, 1);
        ls0 += __shfl_xor_sync(0xffffffffu, ls0, 2);
        ls1 += __shfl_xor_sync(0xffffffffu, ls1, 1);
        ls1 += __shfl_xor_sync(0xffffffffu, ls1, 2);
        l0 = l0 * a0 + ls0;
        l1 = l1 * a1 + ls1;

#pragma unroll
        for (int nt = 0; nt < 8; nt++) {
            o[nt][0] *= a0; o[nt][1] *= a0;
            o[nt][2] *= a1; o[nt][3] *= a1;
        }

        // ---- repack P (accum -> A-frag, in registers) ----
        uint32_t ph[4][4], pl[4][4];
#pragma unroll
        for (int k4 = 0; k4 < 4; k4++) {
            int ta = 2 * k4, tb = ta + 1;
            split2(sa[ta][0], sa[ta][1], ph[k4][0], pl[k4][0]);
            split2(sa[ta][2], sa[ta][3], ph[k4][1], pl[k4][1]);
            split2(sa[tb][0], sa[tb][1], ph[k4][2], pl[k4][2]);
            split2(sa[tb][2], sa[tb][3], ph[k4][3], pl[k4][3]);
        }

        // ---- O += P V (3-pass, V frags via ldmatrix.trans) ----
#pragma unroll
        for (int k4 = 0; k4 < 4; k4++) {
            const int kk = k4 * 16;
#pragma unroll
            for (int p = 0; p < 4; p++) {
                uint32_t wh[4], wl[4];
                uint32_t off = (uint32_t)((kk + vrow) * 72 + p * 16 + vcol8) * 2;
                ldm_x4t(wh, vh + off);
                ldm_x4t(wl, vl + off);
                mma16816(o[2 * p],     ph[k4], wh[0], wh[1]);
                mma16816(o[2 * p],     ph[k4], wl[0], wl[1]);
                mma16816(o[2 * p],     pl[k4], wh[0], wh[1]);
                mma16816(o[2 * p + 1], ph[k4], wh[2], wh[3]);
                mma16816(o[2 * p + 1], ph[k4], wl[2], wl[3]);
                mma16816(o[2 * p + 1], pl[k4], wh[2], wh[3]);
            }
        }
        __syncthreads();   // stage s fully consumed before next refill
    }

    // Epilogue: normalize, store fp32.
    float il0 = 1.f / l0, il1 = 1.f / l1;
    size_t r0 = bT + q0 + qrow;
#pragma unroll
    for (int nt = 0; nt < 8; nt++) {
        int cc = nt * 8 + lc;
        *(float2*)(out + r0 * H_ + cc) =
            make_float2(o[nt][0] * il0, o[nt][1] * il0);
        *(float2*)(out + (r0 + 8) * H_ + cc) =
            make_float2(o[nt][2] * il1, o[nt][3] * il1);
    }
#undef ISSUE_STAGE
}

// ---------------------------------------------------------------------------
// Launch
// ---------------------------------------------------------------------------
extern "C" void kernel_launch(void* const* d_in, const int* in_sizes, int n_in,
                              void* d_out, int out_size)
{
    const float* X   = (const float*)d_in[0];
    const float* Wq  = (const float*)d_in[1];
    const float* Wk  = (const float*)d_in[2];
    const float* Wv  = (const float*)d_in[3];
    const int*   msk = (const int*)d_in[4];
    float* out = (float*)d_out;

    cudaFuncSetAttribute(qkv_mma,
                         cudaFuncAttributeMaxDynamicSharedMemorySize, QKV_SMEM);
    cudaFuncSetAttribute(attn_mma,
                         cudaFuncAttributeMaxDynamicSharedMemorySize, ATTN_SMEM);

    wsplit_kernel<<<768, 256>>>(Wq, Wk, Wv);

    dim3 g1(BT_ / 128, 3);
    qkv_mma<<<g1, 256, QKV_SMEM>>>(X);

    attn_mma<<<256, 128, ATTN_SMEM>>>(msk, out);
}